// round 15
// baseline (speedup 1.0000x reference)
#include <cuda_runtime.h>
#include <cstdint>
#include <math.h>

// Problem dims (fixed by the reference setup_inputs).
#define S_LEN 1024
#define B_N   64
#define I_DIM 1024
#define H_DIM 1024
#define M_TOT (S_LEN * B_N)   // 65536 = S*B

#define NCTA  128             // persistent grid, 1 CTA/SM, all resident
#define NTHR  512             // 16 warps: wm(4) x kq(4)
#define NCH   8               // K chunks of 128
#define NST   3               // cp.async ring stages
#define DPT   2               // chunks in flight

// ---------------------------------------------------------------------------
// Scratch (device globals — no allocation allowed anywhere).
// ---------------------------------------------------------------------------
__device__ float    g_x[(size_t)3 * M_TOT * H_DIM];  // xr/xz/xn  [3][S*B][H]
__device__ uint32_t g_h_tf[2][B_N * H_DIM];          // hidden in tf32 (MMA A), ping-pong
__device__ uint32_t g_rh_tf[B_N * H_DIM];            // (r .* h) in tf32 (MMA A, phase 2)

// Low-latency grid barrier state: per-CTA arrival counters (no atomic
// contention) + a single release word. Monotonic within a launch; reset in
// the prologue (ordered by the one atomic-based barrier).
__device__ unsigned g_arrive[NCTA];
__device__ unsigned g_release;

// prologue atomic-barrier state (zero-init; self-consistent across replays)
__device__ unsigned g_bar_count = 0;
__device__ unsigned g_bar_gen   = 0;

// ---------------------------------------------------------------------------
// tf32 helpers
// ---------------------------------------------------------------------------
__device__ __forceinline__ uint32_t f2tf(float f) {
    uint32_t u;
    asm("cvt.rna.tf32.f32 %0, %1;" : "=r"(u) : "f"(f));
    return u;
}

__device__ __forceinline__ void mma_tf32(float c[4],
        uint32_t a0, uint32_t a1, uint32_t a2, uint32_t a3,
        uint32_t b0, uint32_t b1) {
    asm volatile(
      "mma.sync.aligned.m16n8k8.row.col.f32.tf32.tf32.f32 "
      "{%0,%1,%2,%3}, {%4,%5,%6,%7}, {%8,%9}, {%0,%1,%2,%3};"
      : "+f"(c[0]), "+f"(c[1]), "+f"(c[2]), "+f"(c[3])
      : "r"(a0), "r"(a1), "r"(a2), "r"(a3), "r"(b0), "r"(b1));
}

// ---------------------------------------------------------------------------
// Sync primitives
// ---------------------------------------------------------------------------
__device__ __forceinline__ unsigned ld_acq(unsigned* p) {
    unsigned v;
    asm volatile("ld.acquire.gpu.u32 %0, [%1];" : "=r"(v) : "l"(p) : "memory");
    return v;
}
__device__ __forceinline__ void st_rel(unsigned* p, unsigned v) {
    asm volatile("st.release.gpu.u32 [%0], %1;" :: "l"(p), "r"(v) : "memory");
}

// One-shot prologue barrier (atomic chain; used once per launch).
__device__ __forceinline__ void grid_barrier() {
    __syncthreads();
    if (threadIdx.x == 0) {
        unsigned gen = ld_acq(&g_bar_gen);
        __threadfence();
        unsigned rank = atomicAdd(&g_bar_count, 1u);
        if (rank == NCTA - 1) {
            g_bar_count = 0;
            __threadfence();
            atomicAdd(&g_bar_gen, 1u);
        } else {
            while (ld_acq(&g_bar_gen) == gen) { __nanosleep(16); }
        }
    }
    __syncthreads();
}

// Fast grid barrier: parallel release-stores to per-CTA slots; CTA0 warp0
// polls all 128 slots (4 acquire loads / lane) and release-stores g_release;
// waiters poll one line. No atomic serialization anywhere.
__device__ __forceinline__ void fast_barrier(int c, unsigned target) {
    __syncthreads();
    if (threadIdx.x == 0)
        st_rel(&g_arrive[c], target);
    if (c == 0 && threadIdx.x < 32) {
        const int i0 = threadIdx.x * 4;
        for (;;) {
            unsigned v0 = ld_acq(&g_arrive[i0 + 0]);
            unsigned v1 = ld_acq(&g_arrive[i0 + 1]);
            unsigned v2 = ld_acq(&g_arrive[i0 + 2]);
            unsigned v3 = ld_acq(&g_arrive[i0 + 3]);
            unsigned mn = min(min(v0, v1), min(v2, v3));
            if (__all_sync(0xffffffffu, mn >= target)) break;
        }
        if (threadIdx.x == 0) st_rel(&g_release, target);
    } else if (threadIdx.x == 0) {
        while (ld_acq(&g_release) < target) { }
    }
    __syncthreads();
}

// ---------------------------------------------------------------------------
// Dynamic shared memory. Strides 1028 / 132 (mod 32 == 4) keep the MMA
// fragment reads conflict-free (bank = 4g + tq + const, all distinct).
// A-row pitch 132 words = 528 B = 33 x 16 B -> rows stay 16B-aligned.
// ---------------------------------------------------------------------------
struct SmemRec {
    uint32_t W1[16][1028];     // rows 0-7: W_r cols, 8-15: W_z cols   64.3 KB
    uint32_t W2[8][1028];      // W_n cols                             32.1 KB
    uint32_t A[NST][64][132];  // cp.async A-tile ring (3 x 64 x 128)  99.0 KB
    float    red[3][4][32][8]; // K-quarter reduction (kq 1..3)        12.0 KB
};
#define SMEM_RECUR ((int)sizeof(SmemRec))   // ~207 KB < 227 KB limit

// Issue one K-chunk (64 rows x 128 tf32 words) via cp.async.cg (L1-bypass —
// mandatory: h/rh are written by other SMs and our L1 may hold stale lines).
// 512 threads: 8 threads/row, 64 contiguous bytes each (sector-perfect).
__device__ __forceinline__ void issue_chunk(SmemRec* s, const uint32_t* Atf,
                                            int ci, int st, int arow, int acol) {
    const uint32_t* src = Atf + (size_t)arow * H_DIM + ci * 128 + acol;
    uint32_t dst = (uint32_t)__cvta_generic_to_shared(&s->A[st][arow][acol]);
    #pragma unroll
    for (int i = 0; i < 4; ++i)
        asm volatile("cp.async.cg.shared.global [%0], [%1], 16;"
                     :: "r"(dst + i * 16), "l"(src + i * 4));
    asm volatile("cp.async.commit_group;" ::: "memory");
}

// ---------------------------------------------------------------------------
// Persistent recurrence kernel. 128 CTAs x 512 threads (16 warps =
// 4 row-strips x 4 K-quarters), R13 CTA-wide chunk staging (the R14 per-warp
// scheme regressed). 8 chunks of 128 per phase, 2 fast barriers per step.
// CTA c owns cols j0 = 8c..8c+7 of all three gates; h and z live in
// registers of the kq==0 warps.
// ---------------------------------------------------------------------------
__global__ void __launch_bounds__(NTHR) k_recur(
    const float* __restrict__ whr, const float* __restrict__ whz,
    const float* __restrict__ whn,
    const float* __restrict__ bhr, const float* __restrict__ bhz,
    const float* __restrict__ bhn,
    float* out, int copy_hn)
{
    extern __shared__ unsigned char smem_raw[];
    SmemRec* s = (SmemRec*)smem_raw;

    const int c    = blockIdx.x;
    const int tid  = threadIdx.x;
    const int lane = tid & 31, w = tid >> 5;     // w: 0..15
    const int wm   = w & 3;          // 16-row strip
    const int kq   = w >> 2;         // K quarter (0..3) of each 128-chunk
    const int g    = lane >> 2, tq = lane & 3;
    const int r0   = wm * 16 + g;
    const int arow = tid >> 3;       // staging row (0..63)
    const int acol = (tid & 7) * 16; // staging col (word offset, 64B/thread)
    const int j0   = c * 8;          // this CTA's column base (all gates)

    // ---- prologue: weights -> smem (tf32, swizzled), h0 = 0, flag reset ----
    for (int idx = tid; idx < 16 * 256; idx += NTHR) {
        int row = idx >> 8, c4 = (idx & 255) * 4;
        const float* src = (row < 8) ? (whr + (size_t)(j0 + row) * H_DIM)
                                     : (whz + (size_t)(j0 + row - 8) * H_DIM);
        float4 v = *(const float4*)(src + c4);
        uint32_t* d = &s->W1[row][c4];
        d[0] = f2tf(v.x); d[1] = f2tf(v.y); d[2] = f2tf(v.z); d[3] = f2tf(v.w);
    }
    for (int idx = tid; idx < 8 * 256; idx += NTHR) {
        int row = idx >> 8, c4 = (idx & 255) * 4;
        float4 v = *(const float4*)(whn + (size_t)(j0 + row) * H_DIM + c4);
        uint32_t* d = &s->W2[row][c4];
        d[0] = f2tf(v.x); d[1] = f2tf(v.y); d[2] = f2tf(v.z); d[3] = f2tf(v.w);
    }
    g_h_tf[0][c * NTHR + tid] = 0u;   // 512 per CTA x 128 CTAs = 64K words
    if (tid == 0) {
        g_arrive[c] = 0u;             // replay-safe flag reset
        if (c == 0) g_release = 0u;
    }
    grid_barrier();                   // the only atomic barrier per launch

    // step-invariant biases
    float bpre_r[2], bpre_z[2], bpre_n[2];
    #pragma unroll
    for (int cc = 0; cc < 2; ++cc) {
        bpre_r[cc] = __ldg(&bhr[j0 + tq * 2 + cc]);
        bpre_z[cc] = __ldg(&bhz[j0 + tq * 2 + cc]);
        bpre_n[cc] = __ldg(&bhn[j0 + tq * 2 + cc]);
    }

    float hreg[4] = {0.f, 0.f, 0.f, 0.f};   // own-column f32 hidden state (kq==0)
    float zreg[4];                           // z gate, register-resident (kq==0)
    unsigned bt = 0;                         // fast-barrier target counter

    for (int t = 0; t < S_LEN; ++t) {
        const uint32_t* hin_tf  = g_h_tf[t & 1];
        uint32_t*       hout_tf = g_h_tf[(t + 1) & 1];

        // ========== phase 1: r and z ==========
        {
            float xr_p[4], xz_p[4];
            if (kq == 0) {   // epilogue operand prefetch (hidden behind GEMM)
                const float* xr = g_x + ((size_t)0 * M_TOT + (size_t)t * B_N) * H_DIM;
                const float* xz = g_x + ((size_t)1 * M_TOT + (size_t)t * B_N) * H_DIM;
                #pragma unroll
                for (int hh = 0; hh < 2; ++hh)
                    #pragma unroll
                    for (int cc = 0; cc < 2; ++cc) {
                        int b = wm * 16 + g + hh * 8;
                        int j = j0 + tq * 2 + cc;
                        xr_p[hh * 2 + cc] = __ldcg(&xr[(size_t)b * H_DIM + j]);
                        xz_p[hh * 2 + cc] = __ldcg(&xz[(size_t)b * H_DIM + j]);
                    }
            }

            float accR[2][4] = {}, accZ[2][4] = {};

            #pragma unroll
            for (int d = 0; d < DPT; ++d)
                issue_chunk(s, hin_tf, (c + d) & 7, d, arow, acol);
            for (int i = 0; i < NCH; ++i) {
                if (i < NCH - 1)
                    asm volatile("cp.async.wait_group 1;" ::: "memory");
                else
                    asm volatile("cp.async.wait_group 0;" ::: "memory");
                __syncthreads();
                int nx = i + DPT;
                if (nx < NCH)
                    issue_chunk(s, hin_tf, (c + nx) & 7, nx % NST, arow, acol);
                const int st = i % NST, kb = ((c + i) & 7) * 128;
                #pragma unroll
                for (int m = 0; m < 4; ++m) {
                    int k8 = kq * 32 + m * 8;        // within-chunk col
                    uint32_t a0 = s->A[st][r0    ][k8 + tq];
                    uint32_t a1 = s->A[st][r0 + 8][k8 + tq];
                    uint32_t a2 = s->A[st][r0    ][k8 + tq + 4];
                    uint32_t a3 = s->A[st][r0 + 8][k8 + tq + 4];
                    uint32_t b0r = s->W1[g    ][kb + k8 + tq];
                    uint32_t b1r = s->W1[g    ][kb + k8 + tq + 4];
                    uint32_t b0z = s->W1[8 + g][kb + k8 + tq];
                    uint32_t b1z = s->W1[8 + g][kb + k8 + tq + 4];
                    mma_tf32(accR[m & 1], a0, a1, a2, a3, b0r, b1r);
                    mma_tf32(accZ[m & 1], a0, a1, a2, a3, b0z, b1z);
                }
            }

            // 4-way K reduction through smem; epilogue on kq==0
            if (kq != 0) {
                float* rp = &s->red[kq - 1][wm][lane][0];
                #pragma unroll
                for (int i = 0; i < 4; ++i) {
                    rp[i]     = accR[0][i] + accR[1][i];
                    rp[4 + i] = accZ[0][i] + accZ[1][i];
                }
            }
            __syncthreads();
            if (kq == 0) {
                #pragma unroll
                for (int i = 0; i < 4; ++i) {
                    int hh = i >> 1, cc = i & 1;
                    int b = wm * 16 + g + hh * 8;
                    int j = j0 + tq * 2 + cc;
                    float vr = accR[0][i] + accR[1][i]
                             + s->red[0][wm][lane][i]
                             + s->red[1][wm][lane][i]
                             + s->red[2][wm][lane][i]
                             + xr_p[i] + bpre_r[cc];
                    float vz = accZ[0][i] + accZ[1][i]
                             + s->red[0][wm][lane][4 + i]
                             + s->red[1][wm][lane][4 + i]
                             + s->red[2][wm][lane][4 + i]
                             + xz_p[i] + bpre_z[cc];
                    float sr = 1.f / (1.f + expf(-vr));
                    zreg[i]  = 1.f / (1.f + expf(-vz));
                    g_rh_tf[b * H_DIM + j] = f2tf(sr * hreg[i]);
                }
            }
        }
        fast_barrier(c, ++bt);

        // ========== phase 2: n + gate update ==========
        {
            float xn_p[4];
            if (kq == 0) {
                const float* xn = g_x + ((size_t)2 * M_TOT + (size_t)t * B_N) * H_DIM;
                #pragma unroll
                for (int hh = 0; hh < 2; ++hh)
                    #pragma unroll
                    for (int cc = 0; cc < 2; ++cc) {
                        int b = wm * 16 + g + hh * 8;
                        xn_p[hh * 2 + cc] =
                            __ldcg(&xn[(size_t)b * H_DIM + j0 + tq * 2 + cc]);
                    }
            }

            float acc[2][4] = {};
            #pragma unroll
            for (int d = 0; d < DPT; ++d)
                issue_chunk(s, g_rh_tf, (c + d) & 7, d, arow, acol);
            for (int i = 0; i < NCH; ++i) {
                if (i < NCH - 1)
                    asm volatile("cp.async.wait_group 1;" ::: "memory");
                else
                    asm volatile("cp.async.wait_group 0;" ::: "memory");
                __syncthreads();
                int nx = i + DPT;
                if (nx < NCH)
                    issue_chunk(s, g_rh_tf, (c + nx) & 7, nx % NST, arow, acol);
                const int st = i % NST, kb = ((c + i) & 7) * 128;
                #pragma unroll
                for (int m = 0; m < 4; ++m) {
                    int k8 = kq * 32 + m * 8;
                    uint32_t a0 = s->A[st][r0    ][k8 + tq];
                    uint32_t a1 = s->A[st][r0 + 8][k8 + tq];
                    uint32_t a2 = s->A[st][r0    ][k8 + tq + 4];
                    uint32_t a3 = s->A[st][r0 + 8][k8 + tq + 4];
                    uint32_t b0 = s->W2[g][kb + k8 + tq];
                    uint32_t b1 = s->W2[g][kb + k8 + tq + 4];
                    mma_tf32(acc[m & 1], a0, a1, a2, a3, b0, b1);
                }
            }

            if (kq != 0) {
                float* rp = &s->red[kq - 1][wm][lane][0];
                #pragma unroll
                for (int i = 0; i < 4; ++i)
                    rp[i] = acc[0][i] + acc[1][i];
            }
            __syncthreads();
            if (kq == 0) {
                #pragma unroll
                for (int i = 0; i < 4; ++i) {
                    int hh = i >> 1, cc = i & 1;
                    int b = wm * 16 + g + hh * 8;
                    int j = j0 + tq * 2 + cc;
                    float pre = acc[0][i] + acc[1][i]
                              + s->red[0][wm][lane][i]
                              + s->red[1][wm][lane][i]
                              + s->red[2][wm][lane][i]
                              + xn_p[i] + bpre_n[cc];
                    float nv = tanhf(pre);
                    float hv = (1.f - zreg[i]) * nv + zreg[i] * hreg[i];
                    hreg[i] = hv;
                    hout_tf[b * H_DIM + j] = f2tf(hv);
                    out[((size_t)t * B_N + b) * H_DIM + j] = hv;
                    if (copy_hn && t == S_LEN - 1)
                        out[(size_t)M_TOT * H_DIM + b * H_DIM + j] = hv;
                }
            }
        }
        fast_barrier(c, ++bt);
    }
}

// ---------------------------------------------------------------------------
// Input projections: g_x[g][m][j] = input[m,:] . w_ih_g[j,:] + b_ih_g[j]
// (unchanged; ~2.6 ms)
// ---------------------------------------------------------------------------
__global__ void __launch_bounds__(256) k_xproj(
    const float* __restrict__ input,
    const float* __restrict__ wr, const float* __restrict__ wz,
    const float* __restrict__ wn,
    const float* __restrict__ br, const float* __restrict__ bz,
    const float* __restrict__ bn)
{
    const int ntid  = blockIdx.x;            // 0..23
    const int mBase = blockIdx.y * 128;
    const int gate  = ntid >> 3;             // 0:r 1:z 2:n
    const int jBase = (ntid & 7) * 128;
    const float* W    = (gate == 0) ? wr : ((gate == 1) ? wz : wn);
    const float* bias = (gate == 0) ? br : ((gate == 1) ? bz : bn);

    __shared__ uint32_t As[128][36];
    __shared__ uint32_t Bs[128][36];

    const int tid  = threadIdx.x;
    const int lane = tid & 31;
    const int w    = tid >> 5;
    const int wm   = w & 1;
    const int wn_  = w >> 1;
    const int g    = lane >> 2;
    const int tq   = lane & 3;

    float acc[4][4][4];
    #pragma unroll
    for (int a = 0; a < 4; ++a)
        #pragma unroll
        for (int b = 0; b < 4; ++b)
            #pragma unroll
            for (int cc = 0; cc < 4; ++cc) acc[a][b][cc] = 0.f;

    for (int kc = 0; kc < I_DIM; kc += 32) {
        __syncthreads();
        #pragma unroll
        for (int i = tid; i < 1024; i += 256) {
            int r = i >> 3, c4 = (i & 7) * 4;
            float4 v = *(const float4*)(input + (size_t)(mBase + r) * I_DIM + kc + c4);
            As[r][c4+0] = f2tf(v.x); As[r][c4+1] = f2tf(v.y);
            As[r][c4+2] = f2tf(v.z); As[r][c4+3] = f2tf(v.w);
            float4 u = *(const float4*)(W + (size_t)(jBase + r) * I_DIM + kc + c4);
            Bs[r][c4+0] = f2tf(u.x); Bs[r][c4+1] = f2tf(u.y);
            Bs[r][c4+2] = f2tf(u.z); Bs[r][c4+3] = f2tf(u.w);
        }
        __syncthreads();

        #pragma unroll
        for (int k8 = 0; k8 < 32; k8 += 8) {
            uint32_t af[4][4];
            #pragma unroll
            for (int mt = 0; mt < 4; ++mt) {
                int rr = wm * 64 + mt * 16 + g;
                af[mt][0] = As[rr    ][k8 + tq];
                af[mt][1] = As[rr + 8][k8 + tq];
                af[mt][2] = As[rr    ][k8 + tq + 4];
                af[mt][3] = As[rr + 8][k8 + tq + 4];
            }
            #pragma unroll
            for (int nt = 0; nt < 4; ++nt) {
                int n0 = wn_ * 32 + nt * 8 + g;
                uint32_t b0 = Bs[n0][k8 + tq];
                uint32_t b1 = Bs[n0][k8 + tq + 4];
                #pragma unroll
                for (int mt = 0; mt < 4; ++mt)
                    mma_tf32(acc[mt][nt],
                             af[mt][0], af[mt][1], af[mt][2], af[mt][3], b0, b1);
            }
        }
    }

    #pragma unroll
    for (int mt = 0; mt < 4; ++mt) {
        #pragma unroll
        for (int nt = 0; nt < 4; ++nt) {
            int col = jBase + wn_ * 32 + nt * 8 + tq * 2;
            float b0 = __ldg(&bias[col]);
            float b1 = __ldg(&bias[col + 1]);
            #pragma unroll
            for (int hh = 0; hh < 2; ++hh) {
                int row = mBase + wm * 64 + mt * 16 + g + hh * 8;
                float2 v;
                v.x = acc[mt][nt][hh * 2 + 0] + b0;
                v.y = acc[mt][nt][hh * 2 + 1] + b1;
                *(float2*)(&g_x[((size_t)gate * M_TOT + row) * H_DIM + col]) = v;
            }
        }
    }
}

// ---------------------------------------------------------------------------
extern "C" void kernel_launch(void* const* d_in, const int* in_sizes, int n_in,
                              void* d_out, int out_size) {
    const float* input  = (const float*)d_in[0];
    const float* w_ih_r = (const float*)d_in[1];
    const float* w_hh_r = (const float*)d_in[2];
    const float* w_ih_z = (const float*)d_in[3];
    const float* w_hh_z = (const float*)d_in[4];
    const float* w_ih_n = (const float*)d_in[5];
    const float* w_hh_n = (const float*)d_in[6];
    const float* b_ih_r = (const float*)d_in[7];
    const float* b_hh_r = (const float*)d_in[8];
    const float* b_ih_z = (const float*)d_in[9];
    const float* b_hh_z = (const float*)d_in[10];
    const float* b_ih_n = (const float*)d_in[11];
    const float* b_hh_n = (const float*)d_in[12];
    float* out = (float*)d_out;

    const int copy_hn =
        (out_size >= (int)((size_t)M_TOT * H_DIM + (size_t)B_N * H_DIM)) ? 1 : 0;

    cudaFuncSetAttribute(k_recur, cudaFuncAttributeMaxDynamicSharedMemorySize,
                         SMEM_RECUR);

    // 2 graph nodes total.
    k_xproj<<<dim3(24, 512), 256>>>(input, w_ih_r, w_ih_z, w_ih_n,
                                    b_ih_r, b_ih_z, b_ih_n);
    k_recur<<<NCTA, NTHR, SMEM_RECUR>>>(w_hh_r, w_hh_z, w_hh_n,
                                        b_hh_r, b_hh_z, b_hh_n,
                                        out, copy_hn);
}

// round 16
// speedup vs baseline: 1.4174x; 1.4174x over previous
#include <cuda_runtime.h>
#include <cstdint>
#include <math.h>

// Problem dims (fixed by the reference setup_inputs).
#define S_LEN 1024
#define B_N   64
#define I_DIM 1024
#define H_DIM 1024
#define M_TOT (S_LEN * B_N)   // 65536 = S*B

#define NCTA  128             // persistent grid, 1 CTA/SM, all resident
#define NTHR  512             // 16 warps: wm(4) x kq(4)
#define NCH   16              // K chunks of 64   (R13 memory engine — do not touch)
#define NST   6               // cp.async ring stages
#define DPT   5               // chunks in flight

// ---------------------------------------------------------------------------
// Scratch (device globals — no allocation allowed anywhere).
// ---------------------------------------------------------------------------
__device__ float    g_x[(size_t)3 * M_TOT * H_DIM];  // xr/xz/xn  [3][S*B][H]
__device__ uint32_t g_h_tf[2][B_N * H_DIM];          // hidden in tf32 (MMA A), ping-pong
__device__ uint32_t g_rh_tf[B_N * H_DIM];            // (r .* h) in tf32 (MMA A, phase 2)

// Fast-barrier state: per-CTA arrival counters (parallel release-stores, no
// atomic contention) + one release word. Monotonic within a launch; reset in
// the prologue (ordered by the one-shot atomic barrier).
__device__ unsigned g_arrive[NCTA];
__device__ unsigned g_release;

// prologue atomic-barrier state (zero-init; self-consistent across replays)
__device__ unsigned g_bar_count = 0;
__device__ unsigned g_bar_gen   = 0;

// ---------------------------------------------------------------------------
// tf32 helpers
// ---------------------------------------------------------------------------
__device__ __forceinline__ uint32_t f2tf(float f) {
    uint32_t u;
    asm("cvt.rna.tf32.f32 %0, %1;" : "=r"(u) : "f"(f));
    return u;
}

__device__ __forceinline__ void mma_tf32(float c[4],
        uint32_t a0, uint32_t a1, uint32_t a2, uint32_t a3,
        uint32_t b0, uint32_t b1) {
    asm volatile(
      "mma.sync.aligned.m16n8k8.row.col.f32.tf32.tf32.f32 "
      "{%0,%1,%2,%3}, {%4,%5,%6,%7}, {%8,%9}, {%0,%1,%2,%3};"
      : "+f"(c[0]), "+f"(c[1]), "+f"(c[2]), "+f"(c[3])
      : "r"(a0), "r"(a1), "r"(a2), "r"(a3), "r"(b0), "r"(b1));
}

// ---------------------------------------------------------------------------
// Sync primitives
// ---------------------------------------------------------------------------
__device__ __forceinline__ unsigned ld_acq(unsigned* p) {
    unsigned v;
    asm volatile("ld.acquire.gpu.u32 %0, [%1];" : "=r"(v) : "l"(p) : "memory");
    return v;
}
__device__ __forceinline__ void st_rel(unsigned* p, unsigned v) {
    asm volatile("st.release.gpu.u32 [%0], %1;" :: "l"(p), "r"(v) : "memory");
}

// One-shot prologue barrier (atomic chain; used once per launch).
__device__ __forceinline__ void grid_barrier() {
    __syncthreads();
    if (threadIdx.x == 0) {
        unsigned gen = ld_acq(&g_bar_gen);
        __threadfence();
        unsigned rank = atomicAdd(&g_bar_count, 1u);
        if (rank == NCTA - 1) {
            g_bar_count = 0;
            __threadfence();
            atomicAdd(&g_bar_gen, 1u);
        } else {
            while (ld_acq(&g_bar_gen) == gen) { __nanosleep(16); }
        }
    }
    __syncthreads();
}

// Fast grid barrier: each CTA release-stores its arrival count to its own
// slot (128 parallel stores, no RMW serialization); CTA0 warp0 polls all
// slots (4 acquire loads / lane) and release-stores g_release; waiters poll
// one line with backoff. Release->acquire chain carries the ordering.
__device__ __forceinline__ void fast_barrier(int c, unsigned target) {
    __syncthreads();
    if (c == 0 && threadIdx.x < 32) {
        if (threadIdx.x == 0) st_rel(&g_arrive[0], target);
        const int i0 = threadIdx.x * 4;
        for (;;) {
            unsigned v0 = ld_acq(&g_arrive[i0 + 0]);
            unsigned v1 = ld_acq(&g_arrive[i0 + 1]);
            unsigned v2 = ld_acq(&g_arrive[i0 + 2]);
            unsigned v3 = ld_acq(&g_arrive[i0 + 3]);
            unsigned mn = min(min(v0, v1), min(v2, v3));
            if (__all_sync(0xffffffffu, mn >= target)) break;
            __nanosleep(8);
        }
        if (threadIdx.x == 0) st_rel(&g_release, target);
    } else if (threadIdx.x == 0) {
        st_rel(&g_arrive[c], target);
        while (ld_acq(&g_release) < target) { __nanosleep(8); }
    }
    __syncthreads();
}

// ---------------------------------------------------------------------------
// Dynamic shared memory. Strides 1028 / 68 (mod 32 == 4) keep the MMA
// fragment reads conflict-free (bank = 4g + tq + const, all distinct).
// A-row pitch 68 words = 272 B = 17 x 16 B -> rows stay 16B-aligned.
// ---------------------------------------------------------------------------
struct SmemRec {
    uint32_t W1[16][1028];     // rows 0-7: W_r cols, 8-15: W_z cols   64.3 KB
    uint32_t W2[8][1028];      // W_n cols                             32.1 KB
    uint32_t A[NST][64][68];   // cp.async A-tile ring                102.0 KB
    float    red[3][4][32][8]; // K-quarter reduction (kq 1..3)        12.0 KB
};
#define SMEM_RECUR ((int)sizeof(SmemRec))   // ~210 KB < 227 KB limit

// Issue one K-chunk (64 rows x 64 tf32 words) via cp.async.cg (L1-bypass —
// mandatory: h/rh are written by other SMs and our L1 may hold stale lines).
// 512 threads: 8 threads/row, 2 x 16B each (sector-perfect R13 staging).
__device__ __forceinline__ void issue_chunk(SmemRec* s, const uint32_t* Atf,
                                            int ci, int st, int arow, int aseg) {
    const uint32_t* srcRow = Atf + (size_t)arow * H_DIM + ci * 64;
    uint32_t dbase = (uint32_t)__cvta_generic_to_shared(&s->A[st][arow][0]);
    #pragma unroll
    for (int i = 0; i < 2; ++i) {
        int cw = (aseg + 8 * i) * 4;   // word offset
        asm volatile("cp.async.cg.shared.global [%0], [%1], 16;"
                     :: "r"(dbase + cw * 4), "l"(srcRow + cw));
    }
    asm volatile("cp.async.commit_group;" ::: "memory");
}

__device__ __forceinline__ void wait_pend(int pend) {
    if (pend >= 4)      asm volatile("cp.async.wait_group 4;" ::: "memory");
    else if (pend == 3) asm volatile("cp.async.wait_group 3;" ::: "memory");
    else if (pend == 2) asm volatile("cp.async.wait_group 2;" ::: "memory");
    else if (pend == 1) asm volatile("cp.async.wait_group 1;" ::: "memory");
    else                asm volatile("cp.async.wait_group 0;" ::: "memory");
}

// ---------------------------------------------------------------------------
// Persistent recurrence kernel. EXACT R13 compute/memory structure
// (16 warps = 4 row-strips x 4 K-quarters, CTA-wide chunk staging, per-chunk
// wait_group + __syncthreads). Single change vs R13: the two in-loop grid
// barriers are the contention-free fast_barrier instead of the atomic chain.
// ---------------------------------------------------------------------------
__global__ void __launch_bounds__(NTHR) k_recur(
    const float* __restrict__ whr, const float* __restrict__ whz,
    const float* __restrict__ whn,
    const float* __restrict__ bhr, const float* __restrict__ bhz,
    const float* __restrict__ bhn,
    float* out, int copy_hn)
{
    extern __shared__ unsigned char smem_raw[];
    SmemRec* s = (SmemRec*)smem_raw;

    const int c    = blockIdx.x;
    const int tid  = threadIdx.x;
    const int lane = tid & 31, w = tid >> 5;     // w: 0..15
    const int wm   = w & 3;          // 16-row strip
    const int kq   = w >> 2;         // K quarter (0..3)
    const int g    = lane >> 2, tq = lane & 3;
    const int r0   = wm * 16 + g;
    const int arow = tid >> 3;       // cp.async staging row (0..63)
    const int aseg = tid & 7;        // staging 16B segment base
    const int j0   = c * 8;          // this CTA's column base (all gates)

    // ---- prologue: weights -> smem (tf32, swizzled), h0 = 0, flag reset ----
    for (int idx = tid; idx < 16 * 256; idx += NTHR) {
        int row = idx >> 8, c4 = (idx & 255) * 4;
        const float* src = (row < 8) ? (whr + (size_t)(j0 + row) * H_DIM)
                                     : (whz + (size_t)(j0 + row - 8) * H_DIM);
        float4 v = *(const float4*)(src + c4);
        uint32_t* d = &s->W1[row][c4];
        d[0] = f2tf(v.x); d[1] = f2tf(v.y); d[2] = f2tf(v.z); d[3] = f2tf(v.w);
    }
    for (int idx = tid; idx < 8 * 256; idx += NTHR) {
        int row = idx >> 8, c4 = (idx & 255) * 4;
        float4 v = *(const float4*)(whn + (size_t)(j0 + row) * H_DIM + c4);
        uint32_t* d = &s->W2[row][c4];
        d[0] = f2tf(v.x); d[1] = f2tf(v.y); d[2] = f2tf(v.z); d[3] = f2tf(v.w);
    }
    g_h_tf[0][c * NTHR + tid] = 0u;   // 512 per CTA x 128 CTAs = 64K words
    if (tid == 0) {
        g_arrive[c] = 0u;             // replay-safe flag reset
        if (c == 0) g_release = 0u;
    }
    grid_barrier();                   // the only atomic barrier per launch

    // step-invariant biases
    float bpre_r[2], bpre_z[2], bpre_n[2];
    #pragma unroll
    for (int cc = 0; cc < 2; ++cc) {
        bpre_r[cc] = __ldg(&bhr[j0 + tq * 2 + cc]);
        bpre_z[cc] = __ldg(&bhz[j0 + tq * 2 + cc]);
        bpre_n[cc] = __ldg(&bhn[j0 + tq * 2 + cc]);
    }

    float hreg[4] = {0.f, 0.f, 0.f, 0.f};   // own-column f32 hidden state (kq==0)
    float zreg[4];                           // z gate, register-resident (kq==0)
    unsigned bt = 0;                         // fast-barrier target counter

    for (int t = 0; t < S_LEN; ++t) {
        const uint32_t* hin_tf  = g_h_tf[t & 1];
        uint32_t*       hout_tf = g_h_tf[(t + 1) & 1];

        // ========== phase 1: r and z ==========
        {
            float xr_p[4], xz_p[4];
            if (kq == 0) {   // epilogue operand prefetch (hidden behind GEMM)
                const float* xr = g_x + ((size_t)0 * M_TOT + (size_t)t * B_N) * H_DIM;
                const float* xz = g_x + ((size_t)1 * M_TOT + (size_t)t * B_N) * H_DIM;
                #pragma unroll
                for (int hh = 0; hh < 2; ++hh)
                    #pragma unroll
                    for (int cc = 0; cc < 2; ++cc) {
                        int b = wm * 16 + g + hh * 8;
                        int j = j0 + tq * 2 + cc;
                        xr_p[hh * 2 + cc] = __ldcg(&xr[(size_t)b * H_DIM + j]);
                        xz_p[hh * 2 + cc] = __ldcg(&xz[(size_t)b * H_DIM + j]);
                    }
            }

            float accR[2][4] = {}, accZ[2][4] = {};

            #pragma unroll
            for (int d = 0; d < DPT; ++d)
                issue_chunk(s, hin_tf, (c + d) & 15, d % NST, arow, aseg);
            for (int i = 0; i < NCH; ++i) {
                wait_pend(NCH - 1 - i < DPT - 1 ? NCH - 1 - i : DPT - 1);
                __syncthreads();
                int nx = i + DPT;
                if (nx < NCH)
                    issue_chunk(s, hin_tf, (c + nx) & 15, nx % NST, arow, aseg);
                const int st = i % NST, kb = ((c + i) & 15) * 64;
                #pragma unroll
                for (int m = 0; m < 2; ++m) {
                    int k8 = kq * 16 + m * 8;
                    uint32_t a0 = s->A[st][r0    ][k8 + tq];
                    uint32_t a1 = s->A[st][r0 + 8][k8 + tq];
                    uint32_t a2 = s->A[st][r0    ][k8 + tq + 4];
                    uint32_t a3 = s->A[st][r0 + 8][k8 + tq + 4];
                    uint32_t b0r = s->W1[g    ][kb + k8 + tq];
                    uint32_t b1r = s->W1[g    ][kb + k8 + tq + 4];
                    uint32_t b0z = s->W1[8 + g][kb + k8 + tq];
                    uint32_t b1z = s->W1[8 + g][kb + k8 + tq + 4];
                    mma_tf32(accR[m], a0, a1, a2, a3, b0r, b1r);
                    mma_tf32(accZ[m], a0, a1, a2, a3, b0z, b1z);
                }
            }

            // 4-way K reduction through smem; epilogue on kq==0
            if (kq != 0) {
                float* rp = &s->red[kq - 1][wm][lane][0];
                #pragma unroll
                for (int i = 0; i < 4; ++i) {
                    rp[i]     = accR[0][i] + accR[1][i];
                    rp[4 + i] = accZ[0][i] + accZ[1][i];
                }
            }
            __syncthreads();
            if (kq == 0) {
                #pragma unroll
                for (int i = 0; i < 4; ++i) {
                    int hh = i >> 1, cc = i & 1;
                    int b = wm * 16 + g + hh * 8;
                    int j = j0 + tq * 2 + cc;
                    float vr = accR[0][i] + accR[1][i]
                             + s->red[0][wm][lane][i]
                             + s->red[1][wm][lane][i]
                             + s->red[2][wm][lane][i]
                             + xr_p[i] + bpre_r[cc];
                    float vz = accZ[0][i] + accZ[1][i]
                             + s->red[0][wm][lane][4 + i]
                             + s->red[1][wm][lane][4 + i]
                             + s->red[2][wm][lane][4 + i]
                             + xz_p[i] + bpre_z[cc];
                    float sr = 1.f / (1.f + expf(-vr));
                    zreg[i]  = 1.f / (1.f + expf(-vz));
                    g_rh_tf[b * H_DIM + j] = f2tf(sr * hreg[i]);
                }
            }
        }
        fast_barrier(c, ++bt);

        // ========== phase 2: n + gate update ==========
        {
            float xn_p[4];
            if (kq == 0) {
                const float* xn = g_x + ((size_t)2 * M_TOT + (size_t)t * B_N) * H_DIM;
                #pragma unroll
                for (int hh = 0; hh < 2; ++hh)
                    #pragma unroll
                    for (int cc = 0; cc < 2; ++cc) {
                        int b = wm * 16 + g + hh * 8;
                        xn_p[hh * 2 + cc] =
                            __ldcg(&xn[(size_t)b * H_DIM + j0 + tq * 2 + cc]);
                    }
            }

            float acc[2][4] = {};
            #pragma unroll
            for (int d = 0; d < DPT; ++d)
                issue_chunk(s, g_rh_tf, (c + d) & 15, d % NST, arow, aseg);
            for (int i = 0; i < NCH; ++i) {
                wait_pend(NCH - 1 - i < DPT - 1 ? NCH - 1 - i : DPT - 1);
                __syncthreads();
                int nx = i + DPT;
                if (nx < NCH)
                    issue_chunk(s, g_rh_tf, (c + nx) & 15, nx % NST, arow, aseg);
                const int st = i % NST, kb = ((c + i) & 15) * 64;
                #pragma unroll
                for (int m = 0; m < 2; ++m) {
                    int k8 = kq * 16 + m * 8;
                    uint32_t a0 = s->A[st][r0    ][k8 + tq];
                    uint32_t a1 = s->A[st][r0 + 8][k8 + tq];
                    uint32_t a2 = s->A[st][r0    ][k8 + tq + 4];
                    uint32_t a3 = s->A[st][r0 + 8][k8 + tq + 4];
                    uint32_t b0 = s->W2[g][kb + k8 + tq];
                    uint32_t b1 = s->W2[g][kb + k8 + tq + 4];
                    mma_tf32(acc[m], a0, a1, a2, a3, b0, b1);
                }
            }

            if (kq != 0) {
                float* rp = &s->red[kq - 1][wm][lane][0];
                #pragma unroll
                for (int i = 0; i < 4; ++i)
                    rp[i] = acc[0][i] + acc[1][i];
            }
            __syncthreads();
            if (kq == 0) {
                #pragma unroll
                for (int i = 0; i < 4; ++i) {
                    int hh = i >> 1, cc = i & 1;
                    int b = wm * 16 + g + hh * 8;
                    int j = j0 + tq * 2 + cc;
                    float pre = acc[0][i] + acc[1][i]
                              + s->red[0][wm][lane][i]
                              + s->red[1][wm][lane][i]
                              + s->red[2][wm][lane][i]
                              + xn_p[i] + bpre_n[cc];
                    float nv = tanhf(pre);
                    float hv = (1.f - zreg[i]) * nv + zreg[i] * hreg[i];
                    hreg[i] = hv;
                    hout_tf[b * H_DIM + j] = f2tf(hv);
                    out[((size_t)t * B_N + b) * H_DIM + j] = hv;
                    if (copy_hn && t == S_LEN - 1)
                        out[(size_t)M_TOT * H_DIM + b * H_DIM + j] = hv;
                }
            }
        }
        fast_barrier(c, ++bt);
    }
}

// ---------------------------------------------------------------------------
// Input projections: g_x[g][m][j] = input[m,:] . w_ih_g[j,:] + b_ih_g[j]
// (unchanged; ~2.6 ms)
// ---------------------------------------------------------------------------
__global__ void __launch_bounds__(256) k_xproj(
    const float* __restrict__ input,
    const float* __restrict__ wr, const float* __restrict__ wz,
    const float* __restrict__ wn,
    const float* __restrict__ br, const float* __restrict__ bz,
    const float* __restrict__ bn)
{
    const int ntid  = blockIdx.x;            // 0..23
    const int mBase = blockIdx.y * 128;
    const int gate  = ntid >> 3;             // 0:r 1:z 2:n
    const int jBase = (ntid & 7) * 128;
    const float* W    = (gate == 0) ? wr : ((gate == 1) ? wz : wn);
    const float* bias = (gate == 0) ? br : ((gate == 1) ? bz : bn);

    __shared__ uint32_t As[128][36];
    __shared__ uint32_t Bs[128][36];

    const int tid  = threadIdx.x;
    const int lane = tid & 31;
    const int w    = tid >> 5;
    const int wm   = w & 1;
    const int wn_  = w >> 1;
    const int g    = lane >> 2;
    const int tq   = lane & 3;

    float acc[4][4][4];
    #pragma unroll
    for (int a = 0; a < 4; ++a)
        #pragma unroll
        for (int b = 0; b < 4; ++b)
            #pragma unroll
            for (int cc = 0; cc < 4; ++cc) acc[a][b][cc] = 0.f;

    for (int kc = 0; kc < I_DIM; kc += 32) {
        __syncthreads();
        #pragma unroll
        for (int i = tid; i < 1024; i += 256) {
            int r = i >> 3, c4 = (i & 7) * 4;
            float4 v = *(const float4*)(input + (size_t)(mBase + r) * I_DIM + kc + c4);
            As[r][c4+0] = f2tf(v.x); As[r][c4+1] = f2tf(v.y);
            As[r][c4+2] = f2tf(v.z); As[r][c4+3] = f2tf(v.w);
            float4 u = *(const float4*)(W + (size_t)(jBase + r) * I_DIM + kc + c4);
            Bs[r][c4+0] = f2tf(u.x); Bs[r][c4+1] = f2tf(u.y);
            Bs[r][c4+2] = f2tf(u.z); Bs[r][c4+3] = f2tf(u.w);
        }
        __syncthreads();

        #pragma unroll
        for (int k8 = 0; k8 < 32; k8 += 8) {
            uint32_t af[4][4];
            #pragma unroll
            for (int mt = 0; mt < 4; ++mt) {
                int rr = wm * 64 + mt * 16 + g;
                af[mt][0] = As[rr    ][k8 + tq];
                af[mt][1] = As[rr + 8][k8 + tq];
                af[mt][2] = As[rr    ][k8 + tq + 4];
                af[mt][3] = As[rr + 8][k8 + tq + 4];
            }
            #pragma unroll
            for (int nt = 0; nt < 4; ++nt) {
                int n0 = wn_ * 32 + nt * 8 + g;
                uint32_t b0 = Bs[n0][k8 + tq];
                uint32_t b1 = Bs[n0][k8 + tq + 4];
                #pragma unroll
                for (int mt = 0; mt < 4; ++mt)
                    mma_tf32(acc[mt][nt],
                             af[mt][0], af[mt][1], af[mt][2], af[mt][3], b0, b1);
            }
        }
    }

    #pragma unroll
    for (int mt = 0; mt < 4; ++mt) {
        #pragma unroll
        for (int nt = 0; nt < 4; ++nt) {
            int col = jBase + wn_ * 32 + nt * 8 + tq * 2;
            float b0 = __ldg(&bias[col]);
            float b1 = __ldg(&bias[col + 1]);
            #pragma unroll
            for (int hh = 0; hh < 2; ++hh) {
                int row = mBase + wm * 64 + mt * 16 + g + hh * 8;
                float2 v;
                v.x = acc[mt][nt][hh * 2 + 0] + b0;
                v.y = acc[mt][nt][hh * 2 + 1] + b1;
                *(float2*)(&g_x[((size_t)gate * M_TOT + row) * H_DIM + col]) = v;
            }
        }
    }
}

// ---------------------------------------------------------------------------
extern "C" void kernel_launch(void* const* d_in, const int* in_sizes, int n_in,
                              void* d_out, int out_size) {
    const float* input  = (const float*)d_in[0];
    const float* w_ih_r = (const float*)d_in[1];
    const float* w_hh_r = (const float*)d_in[2];
    const float* w_ih_z = (const float*)d_in[3];
    const float* w_hh_z = (const float*)d_in[4];
    const float* w_ih_n = (const float*)d_in[5];
    const float* w_hh_n = (const float*)d_in[6];
    const float* b_ih_r = (const float*)d_in[7];
    const float* b_hh_r = (const float*)d_in[8];
    const float* b_ih_z = (const float*)d_in[9];
    const float* b_hh_z = (const float*)d_in[10];
    const float* b_ih_n = (const float*)d_in[11];
    const float* b_hh_n = (const float*)d_in[12];
    float* out = (float*)d_out;

    const int copy_hn =
        (out_size >= (int)((size_t)M_TOT * H_DIM + (size_t)B_N * H_DIM)) ? 1 : 0;

    cudaFuncSetAttribute(k_recur, cudaFuncAttributeMaxDynamicSharedMemorySize,
                         SMEM_RECUR);

    // 2 graph nodes total.
    k_xproj<<<dim3(24, 512), 256>>>(input, w_ih_r, w_ih_z, w_ih_n,
                                    b_ih_r, b_ih_z, b_ih_n);
    k_recur<<<NCTA, NTHR, SMEM_RECUR>>>(w_hh_r, w_hh_z, w_hh_n,
                                        b_hh_r, b_hh_z, b_hh_n,
                                        out, copy_hn);
}

// round 17
// speedup vs baseline: 1.5969x; 1.1266x over previous
#include <cuda_runtime.h>
#include <cstdint>
#include <math.h>

// Problem dims (fixed by the reference setup_inputs).
#define S_LEN 1024
#define B_N   64
#define I_DIM 1024
#define H_DIM 1024
#define M_TOT (S_LEN * B_N)   // 65536 = S*B

#define NCTA  128             // persistent grid, 1 CTA/SM, all resident
#define NTHR  512             // 16 warps: 4 groups (wm) x 4 K-quarters (kq)
#define NCH   16              // K chunks of 64   (R13 memory engine)
#define NST   6               // cp.async ring stages
#define DPT   5               // chunks in flight

// ---------------------------------------------------------------------------
// Scratch (device globals — no allocation allowed anywhere).
// ---------------------------------------------------------------------------
__device__ float    g_x[(size_t)3 * M_TOT * H_DIM];  // xr/xz/xn  [3][S*B][H]
__device__ uint32_t g_h_tf[2][B_N * H_DIM];          // hidden in tf32 (MMA A), ping-pong
__device__ uint32_t g_rh_tf[B_N * H_DIM];            // (r .* h) in tf32 (MMA A, phase 2)

// grid-barrier state (zero-init; self-consistent across graph replays)
__device__ unsigned g_bar_count = 0;
__device__ unsigned g_bar_gen   = 0;

// ---------------------------------------------------------------------------
// tf32 helpers
// ---------------------------------------------------------------------------
__device__ __forceinline__ uint32_t f2tf(float f) {
    uint32_t u;
    asm("cvt.rna.tf32.f32 %0, %1;" : "=r"(u) : "f"(f));
    return u;
}

__device__ __forceinline__ void mma_tf32(float c[4],
        uint32_t a0, uint32_t a1, uint32_t a2, uint32_t a3,
        uint32_t b0, uint32_t b1) {
    asm volatile(
      "mma.sync.aligned.m16n8k8.row.col.f32.tf32.tf32.f32 "
      "{%0,%1,%2,%3}, {%4,%5,%6,%7}, {%8,%9}, {%0,%1,%2,%3};"
      : "+f"(c[0]), "+f"(c[1]), "+f"(c[2]), "+f"(c[3])
      : "r"(a0), "r"(a1), "r"(a2), "r"(a3), "r"(b0), "r"(b1));
}

// ---------------------------------------------------------------------------
// Grid barrier (R13 atomic version — fast_barrier regressed in R16).
// ---------------------------------------------------------------------------
__device__ __forceinline__ unsigned ld_acq(unsigned* p) {
    unsigned v;
    asm volatile("ld.acquire.gpu.u32 %0, [%1];" : "=r"(v) : "l"(p) : "memory");
    return v;
}

__device__ __forceinline__ void grid_barrier() {
    __syncthreads();
    if (threadIdx.x == 0) {
        unsigned gen = ld_acq(&g_bar_gen);
        __threadfence();
        unsigned rank = atomicAdd(&g_bar_count, 1u);
        if (rank == NCTA - 1) {
            g_bar_count = 0;
            __threadfence();
            atomicAdd(&g_bar_gen, 1u);
        } else {
            while (ld_acq(&g_bar_gen) == gen) { __nanosleep(16); }
        }
    }
    __syncthreads();
}

// Group barrier: 4-warp (128-thread) named barrier, one per row-group wm.
// Shrinks the per-chunk sync domain from 16 warps to 4.
__device__ __forceinline__ void group_bar(int wm) {
    asm volatile("bar.sync %0, 128;" :: "r"(wm + 1) : "memory");
}

// ---------------------------------------------------------------------------
// Dynamic shared memory. Strides 1028 / 68 (mod 32 == 4) keep the MMA
// fragment reads conflict-free (bank = 4g + tq + const, all distinct).
// A-row pitch 68 words = 272 B = 17 x 16 B -> rows stay 16B-aligned.
// ---------------------------------------------------------------------------
struct SmemRec {
    uint32_t W1[16][1028];     // rows 0-7: W_r cols, 8-15: W_z cols   64.3 KB
    uint32_t W2[8][1028];      // W_n cols                             32.1 KB
    uint32_t A[NST][64][68];   // cp.async A-tile ring                102.0 KB
    float    red[3][4][32][8]; // K-quarter reduction (kq 1..3)        12.0 KB
};
#define SMEM_RECUR ((int)sizeof(SmemRec))   // ~210 KB < 227 KB limit

// Issue one K-chunk slice: thread stages its row (tid>>3, inside its own
// group's 16-row strip) via 2 x 16B cp.async.cg. 8 threads cover 256 B
// contiguous per row (sector-perfect, same as R13). .cg bypasses L1 —
// mandatory: h/rh are produced by other SMs each step.
__device__ __forceinline__ void issue_chunk(SmemRec* s, const uint32_t* Atf,
                                            int ci, int st, int arow, int aseg) {
    const uint32_t* srcRow = Atf + (size_t)arow * H_DIM + ci * 64;
    uint32_t dbase = (uint32_t)__cvta_generic_to_shared(&s->A[st][arow][0]);
    #pragma unroll
    for (int i = 0; i < 2; ++i) {
        int cw = (aseg + 8 * i) * 4;   // word offset
        asm volatile("cp.async.cg.shared.global [%0], [%1], 16;"
                     :: "r"(dbase + cw * 4), "l"(srcRow + cw));
    }
    asm volatile("cp.async.commit_group;" ::: "memory");
}

__device__ __forceinline__ void wait_pend(int pend) {
    if (pend >= 4)      asm volatile("cp.async.wait_group 4;" ::: "memory");
    else if (pend == 3) asm volatile("cp.async.wait_group 3;" ::: "memory");
    else if (pend == 2) asm volatile("cp.async.wait_group 2;" ::: "memory");
    else if (pend == 1) asm volatile("cp.async.wait_group 1;" ::: "memory");
    else                asm volatile("cp.async.wait_group 0;" ::: "memory");
}

// ---------------------------------------------------------------------------
// Persistent recurrence kernel. R13 structure with ONE change: the warp grid
// is remapped to wm = w>>2 (row group), kq = w&3, so each 4-warp group both
// stages AND consumes rows 16wm..16wm+15 of every A chunk, and all per-chunk
// + reduction syncs become group-scoped named barriers (4 warps, one per
// SMSP) instead of CTA-wide __syncthreads. Groups run decoupled inside a
// phase; the two atomic grid barriers per step carry cross-CTA ordering.
// ---------------------------------------------------------------------------
__global__ void __launch_bounds__(NTHR) k_recur(
    const float* __restrict__ whr, const float* __restrict__ whz,
    const float* __restrict__ whn,
    const float* __restrict__ bhr, const float* __restrict__ bhz,
    const float* __restrict__ bhn,
    float* out, int copy_hn)
{
    extern __shared__ unsigned char smem_raw[];
    SmemRec* s = (SmemRec*)smem_raw;

    const int c    = blockIdx.x;
    const int tid  = threadIdx.x;
    const int lane = tid & 31, w = tid >> 5;     // w: 0..15
    const int wm   = w >> 2;         // row group (0..3): rows 16wm..16wm+15
    const int kq   = w & 3;          // K quarter (0..3)
    const int g    = lane >> 2, tq = lane & 3;
    const int r0   = wm * 16 + g;
    const int arow = tid >> 3;       // staging row — lands inside own group
    const int aseg = tid & 7;        // staging 16B segment base
    const int j0   = c * 8;          // this CTA's column base (all gates)

    // ---- prologue: weights -> smem (tf32, swizzled), h0 = 0 ----
    for (int idx = tid; idx < 16 * 256; idx += NTHR) {
        int row = idx >> 8, c4 = (idx & 255) * 4;
        const float* src = (row < 8) ? (whr + (size_t)(j0 + row) * H_DIM)
                                     : (whz + (size_t)(j0 + row - 8) * H_DIM);
        float4 v = *(const float4*)(src + c4);
        uint32_t* d = &s->W1[row][c4];
        d[0] = f2tf(v.x); d[1] = f2tf(v.y); d[2] = f2tf(v.z); d[3] = f2tf(v.w);
    }
    for (int idx = tid; idx < 8 * 256; idx += NTHR) {
        int row = idx >> 8, c4 = (idx & 255) * 4;
        float4 v = *(const float4*)(whn + (size_t)(j0 + row) * H_DIM + c4);
        uint32_t* d = &s->W2[row][c4];
        d[0] = f2tf(v.x); d[1] = f2tf(v.y); d[2] = f2tf(v.z); d[3] = f2tf(v.w);
    }
    g_h_tf[0][c * NTHR + tid] = 0u;   // 512 per CTA x 128 CTAs = 64K words
    grid_barrier();

    // step-invariant biases
    float bpre_r[2], bpre_z[2], bpre_n[2];
    #pragma unroll
    for (int cc = 0; cc < 2; ++cc) {
        bpre_r[cc] = __ldg(&bhr[j0 + tq * 2 + cc]);
        bpre_z[cc] = __ldg(&bhz[j0 + tq * 2 + cc]);
        bpre_n[cc] = __ldg(&bhn[j0 + tq * 2 + cc]);
    }

    float hreg[4] = {0.f, 0.f, 0.f, 0.f};   // own-column f32 hidden state (kq==0)
    float zreg[4];                           // z gate, register-resident (kq==0)

    for (int t = 0; t < S_LEN; ++t) {
        const uint32_t* hin_tf  = g_h_tf[t & 1];
        uint32_t*       hout_tf = g_h_tf[(t + 1) & 1];

        // ========== phase 1: r and z (group-decoupled streaming) ==========
        {
            float xr_p[4], xz_p[4];
            if (kq == 0) {   // epilogue operand prefetch (hidden behind GEMM)
                const float* xr = g_x + ((size_t)0 * M_TOT + (size_t)t * B_N) * H_DIM;
                const float* xz = g_x + ((size_t)1 * M_TOT + (size_t)t * B_N) * H_DIM;
                #pragma unroll
                for (int hh = 0; hh < 2; ++hh)
                    #pragma unroll
                    for (int cc = 0; cc < 2; ++cc) {
                        int b = wm * 16 + g + hh * 8;
                        int j = j0 + tq * 2 + cc;
                        xr_p[hh * 2 + cc] = __ldcg(&xr[(size_t)b * H_DIM + j]);
                        xz_p[hh * 2 + cc] = __ldcg(&xz[(size_t)b * H_DIM + j]);
                    }
            }

            float accR[2][4] = {}, accZ[2][4] = {};

            #pragma unroll
            for (int d = 0; d < DPT; ++d)
                issue_chunk(s, hin_tf, (c + d) & 15, d % NST, arow, aseg);
            for (int i = 0; i < NCH; ++i) {
                wait_pend(NCH - 1 - i < DPT - 1 ? NCH - 1 - i : DPT - 1);
                group_bar(wm);
                int nx = i + DPT;
                if (nx < NCH)
                    issue_chunk(s, hin_tf, (c + nx) & 15, nx % NST, arow, aseg);
                const int st = i % NST, kb = ((c + i) & 15) * 64;
                #pragma unroll
                for (int m = 0; m < 2; ++m) {
                    int k8 = kq * 16 + m * 8;
                    uint32_t a0 = s->A[st][r0    ][k8 + tq];
                    uint32_t a1 = s->A[st][r0 + 8][k8 + tq];
                    uint32_t a2 = s->A[st][r0    ][k8 + tq + 4];
                    uint32_t a3 = s->A[st][r0 + 8][k8 + tq + 4];
                    uint32_t b0r = s->W1[g    ][kb + k8 + tq];
                    uint32_t b1r = s->W1[g    ][kb + k8 + tq + 4];
                    uint32_t b0z = s->W1[8 + g][kb + k8 + tq];
                    uint32_t b1z = s->W1[8 + g][kb + k8 + tq + 4];
                    mma_tf32(accR[m], a0, a1, a2, a3, b0r, b1r);
                    mma_tf32(accZ[m], a0, a1, a2, a3, b0z, b1z);
                }
            }

            // 4-way K reduction through smem (group-internal); epilogue kq==0
            if (kq != 0) {
                float* rp = &s->red[kq - 1][wm][lane][0];
                #pragma unroll
                for (int i = 0; i < 4; ++i) {
                    rp[i]     = accR[0][i] + accR[1][i];
                    rp[4 + i] = accZ[0][i] + accZ[1][i];
                }
            }
            group_bar(wm);
            if (kq == 0) {
                #pragma unroll
                for (int i = 0; i < 4; ++i) {
                    int hh = i >> 1, cc = i & 1;
                    int b = wm * 16 + g + hh * 8;
                    int j = j0 + tq * 2 + cc;
                    float vr = accR[0][i] + accR[1][i]
                             + s->red[0][wm][lane][i]
                             + s->red[1][wm][lane][i]
                             + s->red[2][wm][lane][i]
                             + xr_p[i] + bpre_r[cc];
                    float vz = accZ[0][i] + accZ[1][i]
                             + s->red[0][wm][lane][4 + i]
                             + s->red[1][wm][lane][4 + i]
                             + s->red[2][wm][lane][4 + i]
                             + xz_p[i] + bpre_z[cc];
                    float sr = 1.f / (1.f + expf(-vr));
                    zreg[i]  = 1.f / (1.f + expf(-vz));
                    g_rh_tf[b * H_DIM + j] = f2tf(sr * hreg[i]);
                }
            }
        }
        grid_barrier();

        // ========== phase 2: n + gate update (group-decoupled) ==========
        {
            float xn_p[4];
            if (kq == 0) {
                const float* xn = g_x + ((size_t)2 * M_TOT + (size_t)t * B_N) * H_DIM;
                #pragma unroll
                for (int hh = 0; hh < 2; ++hh)
                    #pragma unroll
                    for (int cc = 0; cc < 2; ++cc) {
                        int b = wm * 16 + g + hh * 8;
                        xn_p[hh * 2 + cc] =
                            __ldcg(&xn[(size_t)b * H_DIM + j0 + tq * 2 + cc]);
                    }
            }

            float acc[2][4] = {};
            #pragma unroll
            for (int d = 0; d < DPT; ++d)
                issue_chunk(s, g_rh_tf, (c + d) & 15, d % NST, arow, aseg);
            for (int i = 0; i < NCH; ++i) {
                wait_pend(NCH - 1 - i < DPT - 1 ? NCH - 1 - i : DPT - 1);
                group_bar(wm);
                int nx = i + DPT;
                if (nx < NCH)
                    issue_chunk(s, g_rh_tf, (c + nx) & 15, nx % NST, arow, aseg);
                const int st = i % NST, kb = ((c + i) & 15) * 64;
                #pragma unroll
                for (int m = 0; m < 2; ++m) {
                    int k8 = kq * 16 + m * 8;
                    uint32_t a0 = s->A[st][r0    ][k8 + tq];
                    uint32_t a1 = s->A[st][r0 + 8][k8 + tq];
                    uint32_t a2 = s->A[st][r0    ][k8 + tq + 4];
                    uint32_t a3 = s->A[st][r0 + 8][k8 + tq + 4];
                    uint32_t b0 = s->W2[g][kb + k8 + tq];
                    uint32_t b1 = s->W2[g][kb + k8 + tq + 4];
                    mma_tf32(acc[m], a0, a1, a2, a3, b0, b1);
                }
            }

            if (kq != 0) {
                float* rp = &s->red[kq - 1][wm][lane][0];
                #pragma unroll
                for (int i = 0; i < 4; ++i)
                    rp[i] = acc[0][i] + acc[1][i];
            }
            group_bar(wm);
            if (kq == 0) {
                #pragma unroll
                for (int i = 0; i < 4; ++i) {
                    int hh = i >> 1, cc = i & 1;
                    int b = wm * 16 + g + hh * 8;
                    int j = j0 + tq * 2 + cc;
                    float pre = acc[0][i] + acc[1][i]
                              + s->red[0][wm][lane][i]
                              + s->red[1][wm][lane][i]
                              + s->red[2][wm][lane][i]
                              + xn_p[i] + bpre_n[cc];
                    float nv = tanhf(pre);
                    float hv = (1.f - zreg[i]) * nv + zreg[i] * hreg[i];
                    hreg[i] = hv;
                    hout_tf[b * H_DIM + j] = f2tf(hv);
                    out[((size_t)t * B_N + b) * H_DIM + j] = hv;
                    if (copy_hn && t == S_LEN - 1)
                        out[(size_t)M_TOT * H_DIM + b * H_DIM + j] = hv;
                }
            }
        }
        grid_barrier();
    }
}

// ---------------------------------------------------------------------------
// Input projections: g_x[g][m][j] = input[m,:] . w_ih_g[j,:] + b_ih_g[j]
// (unchanged; ~2.6 ms)
// ---------------------------------------------------------------------------
__global__ void __launch_bounds__(256) k_xproj(
    const float* __restrict__ input,
    const float* __restrict__ wr, const float* __restrict__ wz,
    const float* __restrict__ wn,
    const float* __restrict__ br, const float* __restrict__ bz,
    const float* __restrict__ bn)
{
    const int ntid  = blockIdx.x;            // 0..23
    const int mBase = blockIdx.y * 128;
    const int gate  = ntid >> 3;             // 0:r 1:z 2:n
    const int jBase = (ntid & 7) * 128;
    const float* W    = (gate == 0) ? wr : ((gate == 1) ? wz : wn);
    const float* bias = (gate == 0) ? br : ((gate == 1) ? bz : bn);

    __shared__ uint32_t As[128][36];
    __shared__ uint32_t Bs[128][36];

    const int tid  = threadIdx.x;
    const int lane = tid & 31;
    const int w    = tid >> 5;
    const int wm   = w & 1;
    const int wn_  = w >> 1;
    const int g    = lane >> 2;
    const int tq   = lane & 3;

    float acc[4][4][4];
    #pragma unroll
    for (int a = 0; a < 4; ++a)
        #pragma unroll
        for (int b = 0; b < 4; ++b)
            #pragma unroll
            for (int cc = 0; cc < 4; ++cc) acc[a][b][cc] = 0.f;

    for (int kc = 0; kc < I_DIM; kc += 32) {
        __syncthreads();
        #pragma unroll
        for (int i = tid; i < 1024; i += 256) {
            int r = i >> 3, c4 = (i & 7) * 4;
            float4 v = *(const float4*)(input + (size_t)(mBase + r) * I_DIM + kc + c4);
            As[r][c4+0] = f2tf(v.x); As[r][c4+1] = f2tf(v.y);
            As[r][c4+2] = f2tf(v.z); As[r][c4+3] = f2tf(v.w);
            float4 u = *(const float4*)(W + (size_t)(jBase + r) * I_DIM + kc + c4);
            Bs[r][c4+0] = f2tf(u.x); Bs[r][c4+1] = f2tf(u.y);
            Bs[r][c4+2] = f2tf(u.z); Bs[r][c4+3] = f2tf(u.w);
        }
        __syncthreads();

        #pragma unroll
        for (int k8 = 0; k8 < 32; k8 += 8) {
            uint32_t af[4][4];
            #pragma unroll
            for (int mt = 0; mt < 4; ++mt) {
                int rr = wm * 64 + mt * 16 + g;
                af[mt][0] = As[rr    ][k8 + tq];
                af[mt][1] = As[rr + 8][k8 + tq];
                af[mt][2] = As[rr    ][k8 + tq + 4];
                af[mt][3] = As[rr + 8][k8 + tq + 4];
            }
            #pragma unroll
            for (int nt = 0; nt < 4; ++nt) {
                int n0 = wn_ * 32 + nt * 8 + g;
                uint32_t b0 = Bs[n0][k8 + tq];
                uint32_t b1 = Bs[n0][k8 + tq + 4];
                #pragma unroll
                for (int mt = 0; mt < 4; ++mt)
                    mma_tf32(acc[mt][nt],
                             af[mt][0], af[mt][1], af[mt][2], af[mt][3], b0, b1);
            }
        }
    }

    #pragma unroll
    for (int mt = 0; mt < 4; ++mt) {
        #pragma unroll
        for (int nt = 0; nt < 4; ++nt) {
            int col = jBase + wn_ * 32 + nt * 8 + tq * 2;
            float b0 = __ldg(&bias[col]);
            float b1 = __ldg(&bias[col + 1]);
            #pragma unroll
            for (int hh = 0; hh < 2; ++hh) {
                int row = mBase + wm * 64 + mt * 16 + g + hh * 8;
                float2 v;
                v.x = acc[mt][nt][hh * 2 + 0] + b0;
                v.y = acc[mt][nt][hh * 2 + 1] + b1;
                *(float2*)(&g_x[((size_t)gate * M_TOT + row) * H_DIM + col]) = v;
            }
        }
    }
}

// ---------------------------------------------------------------------------
extern "C" void kernel_launch(void* const* d_in, const int* in_sizes, int n_in,
                              void* d_out, int out_size) {
    const float* input  = (const float*)d_in[0];
    const float* w_ih_r = (const float*)d_in[1];
    const float* w_hh_r = (const float*)d_in[2];
    const float* w_ih_z = (const float*)d_in[3];
    const float* w_hh_z = (const float*)d_in[4];
    const float* w_ih_n = (const float*)d_in[5];
    const float* w_hh_n = (const float*)d_in[6];
    const float* b_ih_r = (const float*)d_in[7];
    const float* b_hh_r = (const float*)d_in[8];
    const float* b_ih_z = (const float*)d_in[9];
    const float* b_hh_z = (const float*)d_in[10];
    const float* b_ih_n = (const float*)d_in[11];
    const float* b_hh_n = (const float*)d_in[12];
    float* out = (float*)d_out;

    const int copy_hn =
        (out_size >= (int)((size_t)M_TOT * H_DIM + (size_t)B_N * H_DIM)) ? 1 : 0;

    cudaFuncSetAttribute(k_recur, cudaFuncAttributeMaxDynamicSharedMemorySize,
                         SMEM_RECUR);

    // 2 graph nodes total.
    k_xproj<<<dim3(24, 512), 256>>>(input, w_ih_r, w_ih_z, w_ih_n,
                                    b_ih_r, b_ih_z, b_ih_n);
    k_recur<<<NCTA, NTHR, SMEM_RECUR>>>(w_hh_r, w_hh_z, w_hh_n,
                                        b_hh_r, b_hh_z, b_hh_n,
                                        out, copy_hn);
}